// round 2
// baseline (speedup 1.0000x reference)
#include <cuda_runtime.h>
#include <cuda_bf16.h>
#include <cstdint>

// Problem constants
#define HIDDEN 2048
#define INTER  1408
#define NEXP   60
#define TOPK   6

// Scratch (no cudaMalloc allowed)
__device__ float g_inter[TOPK * INTER];   // weighted silu(gate)*up per expert
__device__ int   g_experts[TOPK];

// ---------------------------------------------------------------------------
// Prologue: resolve topk_idx dtype (int64 per reference, but guard int32).
// ---------------------------------------------------------------------------
__global__ void resolve_idx_kernel(const void* __restrict__ idx_raw) {
    const long long* p64 = (const long long*)idx_raw;
    const int*       p32 = (const int*)idx_raw;
    bool ok64 = true;
    for (int k = 0; k < TOPK; k++) {
        long long v = p64[k];
        if (v < 0 || v >= NEXP) ok64 = false;
    }
    for (int k = 0; k < TOPK; k++) {
        g_experts[k] = ok64 ? (int)p64[k] : p32[k];
    }
}

// ---------------------------------------------------------------------------
// Kernel 1: for each (k, i) compute
//   g = dot(gate_row, x), u = dot(up_row, x)
//   g_inter[k*INTER+i] = silu(g) * u * topk_weights[k]
// One warp per output pair. 6*1408 = 8448 warps, 16 float4/lane per row.
// ---------------------------------------------------------------------------
__global__ __launch_bounds__(256) void gateup_kernel(
    const float* __restrict__ x,
    const float* __restrict__ gate_up_all,
    const float* __restrict__ topk_w)
{
    int gwarp = (blockIdx.x * blockDim.x + threadIdx.x) >> 5;
    int lane  = threadIdx.x & 31;
    if (gwarp >= TOPK * INTER) return;

    int k = gwarp / INTER;
    int i = gwarp - k * INTER;
    int e = g_experts[k];

    const float4* xv4  = (const float4*)x;
    const float4* grow = (const float4*)(gate_up_all + ((size_t)e * (2 * INTER) + i) * HIDDEN);
    const float4* urow = (const float4*)(gate_up_all + ((size_t)e * (2 * INTER) + INTER + i) * HIDDEN);

    float dg = 0.f, du = 0.f;
#pragma unroll
    for (int t = 0; t < HIDDEN / 4 / 32; t++) {   // 16 iterations
        int idx = t * 32 + lane;
        float4 xv = xv4[idx];
        float4 gv = grow[idx];
        float4 uv = urow[idx];
        dg += xv.x * gv.x + xv.y * gv.y + xv.z * gv.z + xv.w * gv.w;
        du += xv.x * uv.x + xv.y * uv.y + xv.z * uv.z + xv.w * uv.w;
    }
#pragma unroll
    for (int o = 16; o; o >>= 1) {
        dg += __shfl_xor_sync(0xffffffffu, dg, o);
        du += __shfl_xor_sync(0xffffffffu, du, o);
    }
    if (lane == 0) {
        float s = dg / (1.f + __expf(-dg));        // silu
        g_inter[gwarp] = s * du * topk_w[k];
    }
}

// ---------------------------------------------------------------------------
// Kernel 2: out[h] = sum_k dot(down[e_k, h, :], g_inter[k, :])
// One warp per h (2048 warps). g_inter staged in shared memory per block.
// ---------------------------------------------------------------------------
__global__ __launch_bounds__(256) void down_kernel(
    const float* __restrict__ down_all,
    float* __restrict__ out)
{
    __shared__ float s_inter[TOPK * INTER];

    // Cooperative load of g_inter into smem (33.8 KB)
    for (int idx = threadIdx.x; idx < TOPK * INTER; idx += blockDim.x)
        s_inter[idx] = g_inter[idx];
    __syncthreads();

    int h    = (blockIdx.x * blockDim.x + threadIdx.x) >> 5;
    int lane = threadIdx.x & 31;
    if (h >= HIDDEN) return;

    float acc = 0.f;
#pragma unroll
    for (int k = 0; k < TOPK; k++) {
        int e = g_experts[k];
        const float4* row = (const float4*)(down_all + ((size_t)e * HIDDEN + h) * INTER);
        const float4* iv  = (const float4*)(s_inter + k * INTER);
        float d = 0.f;
#pragma unroll
        for (int t = 0; t < INTER / 4 / 32; t++) { // 11 iterations
            float4 a = row[t * 32 + lane];
            float4 b = iv[t * 32 + lane];
            d += a.x * b.x + a.y * b.y + a.z * b.z + a.w * b.w;
        }
        acc += d;
    }
#pragma unroll
    for (int o = 16; o; o >>= 1)
        acc += __shfl_xor_sync(0xffffffffu, acc, o);
    if (lane == 0) out[h] = acc;
}

// ---------------------------------------------------------------------------
// Inputs (metadata order):
//   0: x_bc1t        float32 [2048]
//   1: topk_idx      int64   [6]
//   2: topk_weights  float32 [6]
//   3: gate_up_all   float32 [60, 2816, 2048]
//   4: down_all      float32 [60, 2048, 1408]
// Output: float32 [2048]
// ---------------------------------------------------------------------------
extern "C" void kernel_launch(void* const* d_in, const int* in_sizes, int n_in,
                              void* d_out, int out_size) {
    const float* x       = (const float*)d_in[0];
    const void*  idx     = d_in[1];
    const float* w       = (const float*)d_in[2];
    const float* gu      = (const float*)d_in[3];
    const float* down    = (const float*)d_in[4];
    float*       out     = (float*)d_out;

    resolve_idx_kernel<<<1, 1>>>(idx);

    int warps1 = TOPK * INTER;                 // 8448
    int blocks1 = (warps1 * 32 + 255) / 256;   // 1056
    gateup_kernel<<<blocks1, 256>>>(x, gu, w);

    int blocks2 = (HIDDEN * 32 + 255) / 256;   // 256
    down_kernel<<<blocks2, 256>>>(down, out);
}

// round 4
// speedup vs baseline: 1.1836x; 1.1836x over previous
#include <cuda_runtime.h>
#include <cuda_bf16.h>
#include <cstdint>

// Problem constants
#define HIDDEN 2048
#define INTER  1408
#define NEXP   60
#define TOPK   6

// Scratch (no cudaMalloc allowed)
__device__ __align__(16) float g_inter[TOPK * INTER]; // weighted silu(gate)*up

// Resolve topk_idx dtype inline: int64 per reference; accept int32 fallback.
__device__ __forceinline__ void resolve_experts(const void* idx_raw, int* s_exp) {
    if (threadIdx.x == 0) {
        const long long* p64 = (const long long*)idx_raw;
        const int*       p32 = (const int*)idx_raw;
        bool ok64 = true;
#pragma unroll
        for (int k = 0; k < TOPK; k++) {
            long long v = p64[k];
            if (v < 0 || v >= NEXP) ok64 = false;
        }
#pragma unroll
        for (int k = 0; k < TOPK; k++)
            s_exp[k] = ok64 ? (int)p64[k] : p32[k];
    }
    __syncthreads();
}

// ---------------------------------------------------------------------------
// Kernel 1: for each (k, i):
//   g = dot(gate_row, x), u = dot(up_row, x)
//   g_inter[k*INTER+i] = silu(g) * u * topk_weights[k]
// One warp per (k,i). 6*1408 = 8448 warps. Streaming loads (__ldcs).
// ---------------------------------------------------------------------------
__global__ __launch_bounds__(256) void gateup_kernel(
    const float* __restrict__ x,
    const void*  __restrict__ idx_raw,
    const float* __restrict__ topk_w,
    const float* __restrict__ gate_up_all)
{
    __shared__ int s_exp[TOPK];
    resolve_experts(idx_raw, s_exp);

    int gwarp = (blockIdx.x * blockDim.x + threadIdx.x) >> 5;
    int lane  = threadIdx.x & 31;
    if (gwarp >= TOPK * INTER) return;

    int k = gwarp / INTER;
    int i = gwarp - k * INTER;
    int e = s_exp[k];

    const float4* xv4  = (const float4*)x;
    const float4* grow = (const float4*)(gate_up_all + ((size_t)e * (2 * INTER) + i) * HIDDEN);
    const float4* urow = (const float4*)(gate_up_all + ((size_t)e * (2 * INTER) + INTER + i) * HIDDEN);

    float dg = 0.f, du = 0.f;
#pragma unroll
    for (int t = 0; t < HIDDEN / 4 / 32; t++) {   // 16 iterations
        int idx = t * 32 + lane;
        float4 xv = xv4[idx];                     // L1/L2-hot
        float4 gv = __ldcs(grow + idx);           // stream-once
        float4 uv = __ldcs(urow + idx);
        dg += xv.x * gv.x + xv.y * gv.y + xv.z * gv.z + xv.w * gv.w;
        du += xv.x * uv.x + xv.y * uv.y + xv.z * uv.z + xv.w * uv.w;
    }
#pragma unroll
    for (int o = 16; o; o >>= 1) {
        dg += __shfl_xor_sync(0xffffffffu, dg, o);
        du += __shfl_xor_sync(0xffffffffu, du, o);
    }
    if (lane == 0) {
        float s = dg / (1.f + __expf(-dg));        // silu
        g_inter[gwarp] = s * du * topk_w[k];
    }
}

// ---------------------------------------------------------------------------
// Kernel 2: out[h] = sum_k dot(down[e_k, h, :], g_inter[k, :])
// 2 warps per h (experts split 3+3), smem pair-reduce. 4096 warps, 512 blocks.
// g_inter staged through shared memory once per block.
// NOTE: shared arrays accessed via float4 MUST be 16B-aligned (R3 trap).
// ---------------------------------------------------------------------------
__global__ __launch_bounds__(256) void down_kernel(
    const void*  __restrict__ idx_raw,
    const float* __restrict__ down_all,
    float* __restrict__ out)
{
    __shared__ __align__(16) float s_inter[TOPK * INTER];
    __shared__ int   s_exp[TOPK];
    __shared__ float s_part[8];

    resolve_experts(idx_raw, s_exp);

    // Cooperative staging of g_inter (33.8 KB) via float4
    {
        const float4* src = (const float4*)g_inter;
        float4*       dst = (float4*)s_inter;
        for (int idx = threadIdx.x; idx < TOPK * INTER / 4; idx += blockDim.x)
            dst[idx] = src[idx];
    }
    __syncthreads();

    int warp  = threadIdx.x >> 5;
    int lane  = threadIdx.x & 31;
    int gwarp = blockIdx.x * 8 + warp;
    int h     = gwarp >> 1;          // 2048 h values
    int half  = gwarp & 1;           // which 3 experts
    if (h >= HIDDEN) return;

    float acc = 0.f;
#pragma unroll
    for (int kk = 0; kk < 3; kk++) {
        int k = half * 3 + kk;
        int e = s_exp[k];
        const float4* row = (const float4*)(down_all + ((size_t)e * HIDDEN + h) * INTER);
        const float4* iv  = (const float4*)(s_inter + k * INTER);
        float d = 0.f;
#pragma unroll
        for (int t = 0; t < INTER / 4 / 32; t++) { // 11 iterations
            float4 a = __ldcs(row + t * 32 + lane);
            float4 b = iv[t * 32 + lane];
            d += a.x * b.x + a.y * b.y + a.z * b.z + a.w * b.w;
        }
        acc += d;
    }
#pragma unroll
    for (int o = 16; o; o >>= 1)
        acc += __shfl_xor_sync(0xffffffffu, acc, o);

    if (lane == 0) s_part[warp] = acc;
    __syncthreads();
    if (lane == 0 && half == 0)
        out[h] = s_part[warp] + s_part[warp + 1];
}

// ---------------------------------------------------------------------------
// Inputs (metadata order):
//   0: x_bc1t        float32 [2048]
//   1: topk_idx      int64   [6]
//   2: topk_weights  float32 [6]
//   3: gate_up_all   float32 [60, 2816, 2048]
//   4: down_all      float32 [60, 2048, 1408]
// Output: float32 [2048]
// ---------------------------------------------------------------------------
extern "C" void kernel_launch(void* const* d_in, const int* in_sizes, int n_in,
                              void* d_out, int out_size) {
    const float* x    = (const float*)d_in[0];
    const void*  idx  = d_in[1];
    const float* w    = (const float*)d_in[2];
    const float* gu   = (const float*)d_in[3];
    const float* down = (const float*)d_in[4];
    float*       out  = (float*)d_out;

    int warps1 = TOPK * INTER;                 // 8448
    int blocks1 = (warps1 * 32 + 255) / 256;   // 1056
    gateup_kernel<<<blocks1, 256>>>(x, idx, w, gu);

    int blocks2 = (HIDDEN * 2 * 32 + 255) / 256;  // 512
    down_kernel<<<blocks2, 256>>>(idx, down, out);
}

// round 5
// speedup vs baseline: 1.2408x; 1.0483x over previous
#include <cuda_runtime.h>
#include <cuda_bf16.h>
#include <cstdint>

// Problem constants
#define HIDDEN 2048
#define INTER  1408
#define NEXP   60
#define TOPK   6

// Scratch (no cudaMalloc allowed)
__device__ __align__(16) float g_inter[TOPK * INTER]; // weighted silu(gate)*up

// Resolve topk_idx dtype inline: int64 per reference; accept int32 fallback.
__device__ __forceinline__ void resolve_experts(const void* idx_raw, int* s_exp) {
    if (threadIdx.x == 0) {
        const long long* p64 = (const long long*)idx_raw;
        const int*       p32 = (const int*)idx_raw;
        bool ok64 = true;
#pragma unroll
        for (int k = 0; k < TOPK; k++) {
            long long v = p64[k];
            if (v < 0 || v >= NEXP) ok64 = false;
        }
#pragma unroll
        for (int k = 0; k < TOPK; k++)
            s_exp[k] = ok64 ? (int)p64[k] : p32[k];
    }
}

// ---------------------------------------------------------------------------
// Kernel 1: for each (k, i):
//   g = dot(gate_row, x), u = dot(up_row, x)
//   g_inter[k*INTER+i] = silu(g) * u * topk_weights[k]
// One warp per (k,i). x staged in smem (kills 67 MB of redundant L1tex/L2
// traffic). Block 0 also zeroes `out` for the down kernel's atomics.
// ---------------------------------------------------------------------------
__global__ __launch_bounds__(256) void gateup_kernel(
    const float* __restrict__ x,
    const void*  __restrict__ idx_raw,
    const float* __restrict__ topk_w,
    const float* __restrict__ gate_up_all,
    float* __restrict__ out)
{
    __shared__ __align__(16) float s_x[HIDDEN];   // 8 KB
    __shared__ int s_exp[TOPK];

    resolve_experts(idx_raw, s_exp);

    // Stage x (512 float4, 2 per thread)
    {
        const float4* src = (const float4*)x;
        float4*       dst = (float4*)s_x;
#pragma unroll
        for (int t = 0; t < HIDDEN / 4 / 256; t++)
            dst[t * 256 + threadIdx.x] = src[t * 256 + threadIdx.x];
    }

    // Block 0 zeroes the output (down_kernel accumulates with atomics)
    if (blockIdx.x == 0) {
#pragma unroll
        for (int t = 0; t < HIDDEN / 256; t++)
            out[t * 256 + threadIdx.x] = 0.f;
    }
    __syncthreads();

    int gwarp = (blockIdx.x * blockDim.x + threadIdx.x) >> 5;
    int lane  = threadIdx.x & 31;
    if (gwarp >= TOPK * INTER) return;

    int k = gwarp / INTER;
    int i = gwarp - k * INTER;
    int e = s_exp[k];

    const float4* xv4  = (const float4*)s_x;
    const float4* grow = (const float4*)(gate_up_all + ((size_t)e * (2 * INTER) + i) * HIDDEN);
    const float4* urow = (const float4*)(gate_up_all + ((size_t)e * (2 * INTER) + INTER + i) * HIDDEN);

    float dg = 0.f, du = 0.f;
#pragma unroll
    for (int t = 0; t < HIDDEN / 4 / 32; t++) {   // 16 iterations
        int idx = t * 32 + lane;
        float4 xv = xv4[idx];                     // smem
        float4 gv = __ldcs(grow + idx);           // stream-once
        float4 uv = __ldcs(urow + idx);
        dg += xv.x * gv.x + xv.y * gv.y + xv.z * gv.z + xv.w * gv.w;
        du += xv.x * uv.x + xv.y * uv.y + xv.z * uv.z + xv.w * uv.w;
    }
#pragma unroll
    for (int o = 16; o; o >>= 1) {
        dg += __shfl_xor_sync(0xffffffffu, dg, o);
        du += __shfl_xor_sync(0xffffffffu, du, o);
    }
    if (lane == 0) {
        float s = dg / (1.f + __expf(-dg));        // silu
        g_inter[gwarp] = s * du * topk_w[k];
    }
}

// ---------------------------------------------------------------------------
// Kernel 2: warp per (h, k) pair: partial = dot(down[e_k, h, :], g_inter[k, :])
// 12288 warps; 11 fully-unrolled LDG.128 per warp (high MLP); g_inter via
// __ldg (L1/L2-hot, 34 KB). Partials combined with atomicAdd (REDG, ~free).
// gwarp = k*HIDDEN + h keeps each expert's matrix streamed contiguously.
// ---------------------------------------------------------------------------
__global__ __launch_bounds__(256) void down_kernel(
    const void*  __restrict__ idx_raw,
    const float* __restrict__ down_all,
    float* __restrict__ out)
{
    __shared__ int s_exp[TOPK];
    resolve_experts(idx_raw, s_exp);
    __syncthreads();

    int warp  = threadIdx.x >> 5;
    int lane  = threadIdx.x & 31;
    int gwarp = blockIdx.x * 8 + warp;      // 0 .. 12287
    if (gwarp >= TOPK * HIDDEN) return;

    int k = gwarp >> 11;                    // / HIDDEN
    int h = gwarp & (HIDDEN - 1);
    int e = s_exp[k];

    const float4* row = (const float4*)(down_all + ((size_t)e * HIDDEN + h) * INTER);
    const float4* iv  = (const float4*)(g_inter + k * INTER);

    float acc = 0.f;
#pragma unroll
    for (int t = 0; t < INTER / 4 / 32; t++) {  // 11 iterations
        float4 a = __ldcs(row + t * 32 + lane); // stream-once weights
        float4 b = __ldg (iv  + t * 32 + lane); // L1/L2-hot activations
        acc += a.x * b.x + a.y * b.y + a.z * b.z + a.w * b.w;
    }
#pragma unroll
    for (int o = 16; o; o >>= 1)
        acc += __shfl_xor_sync(0xffffffffu, acc, o);
    if (lane == 0)
        atomicAdd(out + h, acc);
}

// ---------------------------------------------------------------------------
// Inputs (metadata order):
//   0: x_bc1t        float32 [2048]
//   1: topk_idx      int64   [6]
//   2: topk_weights  float32 [6]
//   3: gate_up_all   float32 [60, 2816, 2048]
//   4: down_all      float32 [60, 2048, 1408]
// Output: float32 [2048]
// ---------------------------------------------------------------------------
extern "C" void kernel_launch(void* const* d_in, const int* in_sizes, int n_in,
                              void* d_out, int out_size) {
    const float* x    = (const float*)d_in[0];
    const void*  idx  = d_in[1];
    const float* w    = (const float*)d_in[2];
    const float* gu   = (const float*)d_in[3];
    const float* down = (const float*)d_in[4];
    float*       out  = (float*)d_out;

    int warps1 = TOPK * INTER;                 // 8448
    int blocks1 = (warps1 * 32 + 255) / 256;   // 1056
    gateup_kernel<<<blocks1, 256>>>(x, idx, w, gu, out);

    int blocks2 = (TOPK * HIDDEN * 32 + 255) / 256;  // 1536
    down_kernel<<<blocks2, 256>>>(idx, down, out);
}